// round 1
// baseline (speedup 1.0000x reference)
#include <cuda_runtime.h>
#include <cuda_bf16.h>
#include <math.h>

// Problem constants
#define BB 128
#define TT 64
#define DD 1024
#define HH 16
#define HDD 64
#define BT (BB*TT)        // 8192
#define PAD 68            // smem row stride for 64-wide tiles (4-way worst conflict)

// Scratch (device globals: allocation-free rule)
__device__ float g_q[BT*DD];
__device__ float g_k[BT*DD];
__device__ float g_v[BT*DD];
__device__ float g_att[BT*DD];

// ---------------------------------------------------------------------------
// Classic tiled SGEMM: C[M,N] = A[M,K] @ W[K,N], all row-major fp32.
// BM=BN=128, BK=16, 256 threads, 8x8 per thread. M%128==0, N%128==0, K%16==0.
// ---------------------------------------------------------------------------
__global__ __launch_bounds__(256) void sgemm_kernel(
    const float* __restrict__ A, const float* __restrict__ W,
    float* __restrict__ C, int M, int N, int K)
{
    __shared__ float sA[16][128];   // A tile transposed: sA[k][m]
    __shared__ float sB[16][128];   // W tile: sB[k][n]

    const int tid = threadIdx.x;
    const int tx = tid & 15;        // 0..15
    const int ty = tid >> 4;        // 0..15
    const int m0 = blockIdx.y * 128;
    const int n0 = blockIdx.x * 128;

    float acc[8][8];
#pragma unroll
    for (int i = 0; i < 8; i++)
#pragma unroll
        for (int j = 0; j < 8; j++) acc[i][j] = 0.f;

    for (int k0 = 0; k0 < K; k0 += 16) {
        // Load A tile 128x16 (transposed into smem)
#pragma unroll
        for (int r = 0; r < 2; r++) {
            int f = tid + r * 256;              // 0..511 float4 id
            int row = f >> 2;                   // 0..127
            int c4  = (f & 3) * 4;              // 0,4,8,12
            float4 v = *reinterpret_cast<const float4*>(
                &A[(size_t)(m0 + row) * K + k0 + c4]);
            sA[c4 + 0][row] = v.x;
            sA[c4 + 1][row] = v.y;
            sA[c4 + 2][row] = v.z;
            sA[c4 + 3][row] = v.w;
        }
        // Load W tile 16x128
#pragma unroll
        for (int r = 0; r < 2; r++) {
            int f = tid + r * 256;
            int row = f >> 5;                   // 0..15
            int c4  = (f & 31) * 4;             // 0..124
            *reinterpret_cast<float4*>(&sB[row][c4]) =
                *reinterpret_cast<const float4*>(
                    &W[(size_t)(k0 + row) * N + n0 + c4]);
        }
        __syncthreads();

#pragma unroll
        for (int kk = 0; kk < 16; kk++) {
            float a[8], b[8];
#pragma unroll
            for (int i = 0; i < 8; i++) a[i] = sA[kk][ty * 8 + i];
#pragma unroll
            for (int j = 0; j < 8; j++) b[j] = sB[kk][tx * 8 + j];
#pragma unroll
            for (int i = 0; i < 8; i++)
#pragma unroll
                for (int j = 0; j < 8; j++)
                    acc[i][j] += a[i] * b[j];
        }
        __syncthreads();
    }

#pragma unroll
    for (int i = 0; i < 8; i++) {
        size_t row = (size_t)(m0 + ty * 8 + i);
#pragma unroll
        for (int j = 0; j < 8; j += 4) {
            float4 v = make_float4(acc[i][j], acc[i][j+1], acc[i][j+2], acc[i][j+3]);
            *reinterpret_cast<float4*>(&C[row * N + n0 + tx * 8 + j]) = v;
        }
    }
}

// ---------------------------------------------------------------------------
// Fused smolgen attention: one block per (b, q). 256 threads.
// logits[h][k] = 0.125*q[h]·k[k,h] + a_q[k]·k[k,h] + q[h]·a_k[k]
// probs = softmax_k; out[h][d] = sum_k p[h][k]*(v[k,h,d] + a_v[k,d])
// ---------------------------------------------------------------------------
__global__ __launch_bounds__(256) void attn_kernel(
    const float* __restrict__ Q, const float* __restrict__ Kt,
    const float* __restrict__ V,
    const float* __restrict__ AQ, const float* __restrict__ AK,
    const float* __restrict__ AV, float* __restrict__ Out)
{
    extern __shared__ float smem[];
    float* sQ  = smem;                  // 1024  [h*64+d]
    float* sAq = sQ  + HH * HDD;        // 64*PAD
    float* sAk = sAq + TT * PAD;        // 64*PAD
    float* sAv = sAk + TT * PAD;        // 64*PAD
    float* sKV = sAv + TT * PAD;        // 64*PAD (K then V, per head)
    float* sLog = sKV + TT * PAD;       // 64
    float* sRed = sLog + TT;            // 256

    const int tid = threadIdx.x;
    const size_t row = (size_t)blockIdx.x;     // b*T + qi
    const int b = blockIdx.x >> 6;

    // Load q row (1024 floats = 256 float4, one per thread)
    {
        const float4* src = reinterpret_cast<const float4*>(Q + row * DD);
        reinterpret_cast<float4*>(sQ)[tid] = src[tid];
    }
    // Load a_q / a_k / a_v rows: contiguous [64][64] -> padded smem
    {
        const float4* q4 = reinterpret_cast<const float4*>(AQ + row * TT * HDD);
        const float4* k4 = reinterpret_cast<const float4*>(AK + row * TT * HDD);
        const float4* v4 = reinterpret_cast<const float4*>(AV + row * TT * HDD);
#pragma unroll
        for (int r = 0; r < 4; r++) {
            int f  = tid + r * 256;     // 0..1023 float4 id
            int kk = f >> 4;
            int c4 = (f & 15) * 4;
            *reinterpret_cast<float4*>(&sAq[kk * PAD + c4]) = q4[f];
            *reinterpret_cast<float4*>(&sAk[kk * PAD + c4]) = k4[f];
            *reinterpret_cast<float4*>(&sAv[kk * PAD + c4]) = v4[f];
        }
    }
    __syncthreads();

    const int lk  = tid >> 2;           // logits: k index 0..63
    const int lp  = tid & 3;            // logits: d-quarter 0..3
    const int od  = tid & 63;           // output: d index
    const int okp = tid >> 6;           // output: k-quarter

    for (int h = 0; h < HH; h++) {
        // --- load K tile for head h: k[b, 0..63, h, 0..63] ---
        {
            const float* kb = Kt + (size_t)b * TT * DD + h * HDD;
#pragma unroll
            for (int r = 0; r < 4; r++) {
                int f  = tid + r * 256;
                int kk = f >> 4;
                int c4 = (f & 15) * 4;
                float4 v = *reinterpret_cast<const float4*>(kb + (size_t)kk * DD + c4);
                *reinterpret_cast<float4*>(&sKV[kk * PAD + c4]) = v;
            }
        }
        __syncthreads();

        // --- logits ---
        {
            const float* qh = sQ + h * HDD;
            float c = 0.f, bq = 0.f, bk = 0.f;
            const int dbase = lp * 16;
#pragma unroll
            for (int i = 0; i < 16; i++) {
                int d = dbase + i;
                float kv = sKV[lk * PAD + d];
                float qv = qh[d];
                c  += qv * kv;
                bq += sAq[lk * PAD + d] * kv;
                bk += qv * sAk[lk * PAD + d];
            }
            float l = c * 0.125f + bq + bk;
            l += __shfl_xor_sync(0xffffffffu, l, 1);
            l += __shfl_xor_sync(0xffffffffu, l, 2);
            if (lp == 0) sLog[lk] = l;
        }
        __syncthreads();

        // --- softmax over 64 logits (warp 0) ---
        if (tid < 32) {
            float a = sLog[tid], b2 = sLog[tid + 32];
            float m = fmaxf(a, b2);
#pragma unroll
            for (int o = 16; o; o >>= 1)
                m = fmaxf(m, __shfl_xor_sync(0xffffffffu, m, o));
            float ea = __expf(a - m), eb = __expf(b2 - m);
            float s = ea + eb;
#pragma unroll
            for (int o = 16; o; o >>= 1)
                s += __shfl_xor_sync(0xffffffffu, s, o);
            float inv = 1.0f / s;
            sLog[tid] = ea * inv;
            sLog[tid + 32] = eb * inv;
        }
        __syncthreads();

        // --- load V tile (overwrite sKV) ---
        {
            const float* vb = V + (size_t)b * TT * DD + h * HDD;
#pragma unroll
            for (int r = 0; r < 4; r++) {
                int f  = tid + r * 256;
                int kk = f >> 4;
                int c4 = (f & 15) * 4;
                float4 v = *reinterpret_cast<const float4*>(vb + (size_t)kk * DD + c4);
                *reinterpret_cast<float4*>(&sKV[kk * PAD + c4]) = v;
            }
        }
        __syncthreads();

        // --- output: out[h][d] = sum_k p[k]*(V[k][d] + a_v[k][d]) ---
        {
            float acc = 0.f;
#pragma unroll
            for (int i = 0; i < 16; i++) {
                int k = okp * 16 + i;
                float p = sLog[k];
                acc += p * (sKV[k * PAD + od] + sAv[k * PAD + od]);
            }
            sRed[tid] = acc;
        }
        __syncthreads();
        if (tid < 64) {
            float o = sRed[tid] + sRed[tid + 64] + sRed[tid + 128] + sRed[tid + 192];
            Out[row * DD + h * HDD + tid] = o;
        }
        __syncthreads();
    }
}

// ---------------------------------------------------------------------------
extern "C" void kernel_launch(void* const* d_in, const int* in_sizes, int n_in,
                              void* d_out, int out_size)
{
    const float* x  = (const float*)d_in[0];
    const float* aq = (const float*)d_in[1];
    const float* ak = (const float*)d_in[2];
    const float* av = (const float*)d_in[3];
    const float* Wq = (const float*)d_in[4];
    const float* Wk = (const float*)d_in[5];
    const float* Wv = (const float*)d_in[6];
    const float* Wo = (const float*)d_in[7];
    float* out = (float*)d_out;

    float *pq, *pk, *pv, *patt;
    cudaGetSymbolAddress((void**)&pq,   g_q);
    cudaGetSymbolAddress((void**)&pk,   g_k);
    cudaGetSymbolAddress((void**)&pv,   g_v);
    cudaGetSymbolAddress((void**)&patt, g_att);

    dim3 ggrid(DD / 128, BT / 128);   // (8, 64)

    sgemm_kernel<<<ggrid, 256>>>(x, Wq, pq, BT, DD, DD);
    sgemm_kernel<<<ggrid, 256>>>(x, Wk, pk, BT, DD, DD);
    sgemm_kernel<<<ggrid, 256>>>(x, Wv, pv, BT, DD, DD);

    const int smem_bytes = (HH*HDD + 4 * TT * PAD + TT + 256) * (int)sizeof(float);
    cudaFuncSetAttribute((const void*)attn_kernel,
                         cudaFuncAttributeMaxDynamicSharedMemorySize, smem_bytes);
    attn_kernel<<<BT, 256, smem_bytes>>>(pq, pk, pv, aq, ak, av, patt);

    sgemm_kernel<<<ggrid, 256>>>(patt, Wo, out, BT, DD, DD);
}

// round 2
// speedup vs baseline: 1.8582x; 1.8582x over previous
#include <cuda_runtime.h>
#include <cuda_bf16.h>
#include <math.h>

// Problem constants
#define BB 128
#define TT 64
#define DD 1024
#define HH 16
#define HDD 64
#define BT (BB*TT)        // 8192
#define PAD 68

// Scratch (device globals: allocation-free rule)
__device__ float g_q[BT*DD];
__device__ float g_k[BT*DD];
__device__ float g_v[BT*DD];
__device__ float g_att[BT*DD];

__device__ __forceinline__ float to_tf32(float x) {
    float r;
    asm("cvt.rna.tf32.f32 %0, %1;" : "=f"(r) : "f"(x));
    return r;
}

__device__ __forceinline__ void mma_tf32(float c[4], const unsigned a[4], const unsigned b[2]) {
    asm volatile(
        "mma.sync.aligned.m16n8k8.row.col.f32.tf32.tf32.f32 "
        "{%0,%1,%2,%3}, {%4,%5,%6,%7}, {%8,%9}, {%0,%1,%2,%3};"
        : "+f"(c[0]), "+f"(c[1]), "+f"(c[2]), "+f"(c[3])
        : "r"(a[0]), "r"(a[1]), "r"(a[2]), "r"(a[3]),
          "r"(b[0]), "r"(b[1]));
}

// ---------------------------------------------------------------------------
// TF32 tensor-core GEMM: C[M,N] = A[M,K] @ W[K,N], row-major fp32 in/out.
// BM=BN=128, BK=32, 256 threads (8 warps, 4m x 2n), warp tile 32x64.
// ---------------------------------------------------------------------------
__global__ __launch_bounds__(256) void tf32_gemm_kernel(
    const float* __restrict__ A, const float* __restrict__ W,
    float* __restrict__ C, int M, int N, int K)
{
    __shared__ float sA[128][36];   // A tile [m][k], pad->conflict-free frags
    __shared__ float sB[32][136];   // W tile [k][n], pad 8 -> conflict-free frags

    const int tid  = threadIdx.x;
    const int lane = tid & 31;
    const int wid  = tid >> 5;
    const int wm   = (wid & 3) * 32;   // warp m offset in tile
    const int wn   = (wid >> 2) * 64;  // warp n offset in tile
    const int g    = lane >> 2;        // 0..7
    const int t    = lane & 3;         // 0..3

    const int m0 = blockIdx.y * 128;
    const int n0 = blockIdx.x * 128;

    float acc[2][8][4];
#pragma unroll
    for (int mt = 0; mt < 2; mt++)
#pragma unroll
        for (int nt = 0; nt < 8; nt++)
#pragma unroll
            for (int i = 0; i < 4; i++) acc[mt][nt][i] = 0.f;

    for (int k0 = 0; k0 < K; k0 += 32) {
        // Load A tile 128x32 (row-major into sA[m][k]), convert to tf32
#pragma unroll
        for (int r = 0; r < 4; r++) {
            int f   = tid + r * 256;      // float4 id 0..1023
            int row = f >> 3;             // 0..127
            int c4  = (f & 7) * 4;        // 0..28
            float4 v = *reinterpret_cast<const float4*>(
                &A[(size_t)(m0 + row) * K + k0 + c4]);
            v.x = to_tf32(v.x); v.y = to_tf32(v.y);
            v.z = to_tf32(v.z); v.w = to_tf32(v.w);
            *reinterpret_cast<float4*>(&sA[row][c4]) = v;
        }
        // Load W tile 32x128 into sB[k][n], convert to tf32
#pragma unroll
        for (int r = 0; r < 4; r++) {
            int f   = tid + r * 256;
            int row = f >> 5;             // 0..31
            int c4  = (f & 31) * 4;       // 0..124
            float4 v = *reinterpret_cast<const float4*>(
                &W[(size_t)(k0 + row) * N + n0 + c4]);
            v.x = to_tf32(v.x); v.y = to_tf32(v.y);
            v.z = to_tf32(v.z); v.w = to_tf32(v.w);
            *reinterpret_cast<float4*>(&sB[row][c4]) = v;
        }
        __syncthreads();

#pragma unroll
        for (int ks = 0; ks < 4; ks++) {
            const int kb = ks * 8;
            unsigned af[2][4];
#pragma unroll
            for (int mt = 0; mt < 2; mt++) {
                const int row = wm + mt * 16;
                af[mt][0] = __float_as_uint(sA[row + g    ][kb + t    ]);
                af[mt][1] = __float_as_uint(sA[row + g + 8][kb + t    ]);
                af[mt][2] = __float_as_uint(sA[row + g    ][kb + t + 4]);
                af[mt][3] = __float_as_uint(sA[row + g + 8][kb + t + 4]);
            }
            unsigned bf[8][2];
#pragma unroll
            for (int nt = 0; nt < 8; nt++) {
                const int col = wn + nt * 8 + g;
                bf[nt][0] = __float_as_uint(sB[kb + t    ][col]);
                bf[nt][1] = __float_as_uint(sB[kb + t + 4][col]);
            }
#pragma unroll
            for (int mt = 0; mt < 2; mt++)
#pragma unroll
                for (int nt = 0; nt < 8; nt++)
                    mma_tf32(acc[mt][nt], af[mt], bf[nt]);
        }
        __syncthreads();
    }

    // Epilogue: c0:(g,2t) c1:(g,2t+1) c2:(g+8,2t) c3:(g+8,2t+1)
#pragma unroll
    for (int mt = 0; mt < 2; mt++) {
#pragma unroll
        for (int nt = 0; nt < 8; nt++) {
            const size_t row = (size_t)(m0 + wm + mt * 16 + g);
            const int    col = n0 + wn + nt * 8 + 2 * t;
            float2 lo = make_float2(acc[mt][nt][0], acc[mt][nt][1]);
            float2 hi = make_float2(acc[mt][nt][2], acc[mt][nt][3]);
            *reinterpret_cast<float2*>(&C[row * N + col])            = lo;
            *reinterpret_cast<float2*>(&C[(row + 8) * N + col])      = hi;
        }
    }
}

// ---------------------------------------------------------------------------
// Fused smolgen attention: one block per (b, q). 256 threads.
// ---------------------------------------------------------------------------
__global__ __launch_bounds__(256) void attn_kernel(
    const float* __restrict__ Q, const float* __restrict__ Kt,
    const float* __restrict__ V,
    const float* __restrict__ AQ, const float* __restrict__ AK,
    const float* __restrict__ AV, float* __restrict__ Out)
{
    extern __shared__ float smem[];
    float* sQ  = smem;                  // 1024
    float* sAq = sQ  + HH * HDD;
    float* sAk = sAq + TT * PAD;
    float* sAv = sAk + TT * PAD;
    float* sKV = sAv + TT * PAD;
    float* sLog = sKV + TT * PAD;       // 64
    float* sRed = sLog + TT;            // 256

    const int tid = threadIdx.x;
    const size_t row = (size_t)blockIdx.x;
    const int b = blockIdx.x >> 6;

    {
        const float4* src = reinterpret_cast<const float4*>(Q + row * DD);
        reinterpret_cast<float4*>(sQ)[tid] = src[tid];
    }
    {
        const float4* q4 = reinterpret_cast<const float4*>(AQ + row * TT * HDD);
        const float4* k4 = reinterpret_cast<const float4*>(AK + row * TT * HDD);
        const float4* v4 = reinterpret_cast<const float4*>(AV + row * TT * HDD);
#pragma unroll
        for (int r = 0; r < 4; r++) {
            int f  = tid + r * 256;
            int kk = f >> 4;
            int c4 = (f & 15) * 4;
            *reinterpret_cast<float4*>(&sAq[kk * PAD + c4]) = q4[f];
            *reinterpret_cast<float4*>(&sAk[kk * PAD + c4]) = k4[f];
            *reinterpret_cast<float4*>(&sAv[kk * PAD + c4]) = v4[f];
        }
    }
    __syncthreads();

    const int lk  = tid >> 2;           // 0..63
    const int lp  = tid & 3;            // 0..3
    const int od  = tid & 63;
    const int okp = tid >> 6;

    for (int h = 0; h < HH; h++) {
        {
            const float* kb = Kt + (size_t)b * TT * DD + h * HDD;
#pragma unroll
            for (int r = 0; r < 4; r++) {
                int f  = tid + r * 256;
                int kk = f >> 4;
                int c4 = (f & 15) * 4;
                float4 v = *reinterpret_cast<const float4*>(kb + (size_t)kk * DD + c4);
                *reinterpret_cast<float4*>(&sKV[kk * PAD + c4]) = v;
            }
        }
        __syncthreads();

        // logits: d = lp + 4*i  (bank = (4*lk + lp) % 32, bijective -> conflict-free)
        {
            const float* qh = sQ + h * HDD;
            float c = 0.f, bq = 0.f, bk = 0.f;
#pragma unroll
            for (int i = 0; i < 16; i++) {
                int d = lp + 4 * i;
                float kv = sKV[lk * PAD + d];
                float qv = qh[d];
                c  += qv * kv;
                bq += sAq[lk * PAD + d] * kv;
                bk += qv * sAk[lk * PAD + d];
            }
            float l = c * 0.125f + bq + bk;
            l += __shfl_xor_sync(0xffffffffu, l, 1);
            l += __shfl_xor_sync(0xffffffffu, l, 2);
            if (lp == 0) sLog[lk] = l;
        }
        __syncthreads();

        if (tid < 32) {
            float a = sLog[tid], b2 = sLog[tid + 32];
            float m = fmaxf(a, b2);
#pragma unroll
            for (int o = 16; o; o >>= 1)
                m = fmaxf(m, __shfl_xor_sync(0xffffffffu, m, o));
            float ea = __expf(a - m), eb = __expf(b2 - m);
            float s = ea + eb;
#pragma unroll
            for (int o = 16; o; o >>= 1)
                s += __shfl_xor_sync(0xffffffffu, s, o);
            float inv = 1.0f / s;
            sLog[tid] = ea * inv;
            sLog[tid + 32] = eb * inv;
        }
        __syncthreads();

        {
            const float* vb = V + (size_t)b * TT * DD + h * HDD;
#pragma unroll
            for (int r = 0; r < 4; r++) {
                int f  = tid + r * 256;
                int kk = f >> 4;
                int c4 = (f & 15) * 4;
                float4 v = *reinterpret_cast<const float4*>(vb + (size_t)kk * DD + c4);
                *reinterpret_cast<float4*>(&sKV[kk * PAD + c4]) = v;
            }
        }
        __syncthreads();

        {
            float acc = 0.f;
#pragma unroll
            for (int i = 0; i < 16; i++) {
                int k = okp * 16 + i;
                float p = sLog[k];
                acc += p * (sKV[k * PAD + od] + sAv[k * PAD + od]);
            }
            sRed[tid] = acc;
        }
        __syncthreads();
        if (tid < 64) {
            float o = sRed[tid] + sRed[tid + 64] + sRed[tid + 128] + sRed[tid + 192];
            Out[row * DD + h * HDD + tid] = o;
        }
        __syncthreads();
    }
}

// ---------------------------------------------------------------------------
extern "C" void kernel_launch(void* const* d_in, const int* in_sizes, int n_in,
                              void* d_out, int out_size)
{
    const float* x  = (const float*)d_in[0];
    const float* aq = (const float*)d_in[1];
    const float* ak = (const float*)d_in[2];
    const float* av = (const float*)d_in[3];
    const float* Wq = (const float*)d_in[4];
    const float* Wk = (const float*)d_in[5];
    const float* Wv = (const float*)d_in[6];
    const float* Wo = (const float*)d_in[7];
    float* out = (float*)d_out;

    float *pq, *pk, *pv, *patt;
    cudaGetSymbolAddress((void**)&pq,   g_q);
    cudaGetSymbolAddress((void**)&pk,   g_k);
    cudaGetSymbolAddress((void**)&pv,   g_v);
    cudaGetSymbolAddress((void**)&patt, g_att);

    dim3 ggrid(DD / 128, BT / 128);   // (8, 64)

    tf32_gemm_kernel<<<ggrid, 256>>>(x, Wq, pq, BT, DD, DD);
    tf32_gemm_kernel<<<ggrid, 256>>>(x, Wk, pk, BT, DD, DD);
    tf32_gemm_kernel<<<ggrid, 256>>>(x, Wv, pv, BT, DD, DD);

    const int smem_bytes = (HH*HDD + 4 * TT * PAD + TT + 256) * (int)sizeof(float);
    cudaFuncSetAttribute((const void*)attn_kernel,
                         cudaFuncAttributeMaxDynamicSharedMemorySize, smem_bytes);
    attn_kernel<<<BT, 256, smem_bytes>>>(pq, pk, pv, aq, ak, av, patt);

    tf32_gemm_kernel<<<ggrid, 256>>>(patt, Wo, out, BT, DD, DD);
}

// round 3
// speedup vs baseline: 2.0805x; 1.1196x over previous
#include <cuda_runtime.h>
#include <cuda_bf16.h>
#include <math.h>

// Problem constants
#define BB 128
#define TT 64
#define DD 1024
#define HH 16
#define HDD 64
#define BT (BB*TT)        // 8192
#define PAD 68

// Scratch (device globals: allocation-free rule)
__device__ float g_q[BT*DD];
__device__ float g_k[BT*DD];
__device__ float g_v[BT*DD];
__device__ float g_att[BT*DD];

__device__ __forceinline__ float to_tf32(float x) {
    float r;
    asm("cvt.rna.tf32.f32 %0, %1;" : "=f"(r) : "f"(x));
    return r;
}
__device__ __forceinline__ unsigned tf32_bits(float x) {
    return __float_as_uint(to_tf32(x));
}

__device__ __forceinline__ void mma_tf32(float c[4], const unsigned a[4], const unsigned b[2]) {
    asm volatile(
        "mma.sync.aligned.m16n8k8.row.col.f32.tf32.tf32.f32 "
        "{%0,%1,%2,%3}, {%4,%5,%6,%7}, {%8,%9}, {%0,%1,%2,%3};"
        : "+f"(c[0]), "+f"(c[1]), "+f"(c[2]), "+f"(c[3])
        : "r"(a[0]), "r"(a[1]), "r"(a[2]), "r"(a[3]),
          "r"(b[0]), "r"(b[1]));
}

__device__ __forceinline__ void cp_async16(void* smem, const void* gmem) {
    unsigned s = (unsigned)__cvta_generic_to_shared(smem);
    asm volatile("cp.async.ca.shared.global [%0], [%1], 16;\n" :: "r"(s), "l"(gmem));
}
#define CP_COMMIT() asm volatile("cp.async.commit_group;\n" ::: "memory")
#define CP_WAIT0()  asm volatile("cp.async.wait_group 0;\n" ::: "memory")

// ---------------------------------------------------------------------------
// TF32 tensor-core GEMM, cp.async double-buffered.
// C[M,N] = A[M,K] @ W[K,N], row-major fp32. BM=BN=128, BK=32, 256 thr.
// Dynamic smem: sA[2][128][36] + sB[2][32][136]  (tf32 cvt at fragment load)
// ---------------------------------------------------------------------------
#define SA_ST 4608   // 128*36
#define SB_ST 4352   // 32*136
#define GEMM_SMEM ((2*SA_ST + 2*SB_ST) * 4)

__global__ __launch_bounds__(256) void tf32_gemm_kernel(
    const float* __restrict__ A, const float* __restrict__ W,
    float* __restrict__ C, int M, int N, int K)
{
    extern __shared__ float dsm[];
    float* sAb = dsm;                 // [2][128][36]
    float* sBb = dsm + 2 * SA_ST;     // [2][32][136]

    const int tid  = threadIdx.x;
    const int lane = tid & 31;
    const int wid  = tid >> 5;
    const int wm   = (wid & 3) * 32;
    const int wn   = (wid >> 2) * 64;
    const int g    = lane >> 2;
    const int t    = lane & 3;

    const int m0 = blockIdx.y * 128;
    const int n0 = blockIdx.x * 128;

    float acc[2][8][4];
#pragma unroll
    for (int mt = 0; mt < 2; mt++)
#pragma unroll
        for (int nt = 0; nt < 8; nt++)
#pragma unroll
            for (int i = 0; i < 4; i++) acc[mt][nt][i] = 0.f;

    // stage loader (cp.async)
    auto load_stage = [&](int st, int k0) {
        float* sA = sAb + st * SA_ST;
        float* sB = sBb + st * SB_ST;
#pragma unroll
        for (int r = 0; r < 4; r++) {
            int f   = tid + r * 256;
            int row = f >> 3;            // 0..127
            int c4  = (f & 7) * 4;       // 0..28
            cp_async16(&sA[row * 36 + c4],
                       &A[(size_t)(m0 + row) * K + k0 + c4]);
        }
#pragma unroll
        for (int r = 0; r < 4; r++) {
            int f   = tid + r * 256;
            int row = f >> 5;            // 0..31
            int c4  = (f & 31) * 4;      // 0..124
            cp_async16(&sB[row * 136 + c4],
                       &W[(size_t)(k0 + row) * N + n0 + c4]);
        }
    };

    load_stage(0, 0);
    CP_COMMIT();
    CP_WAIT0();
    __syncthreads();

    int st = 0;
    for (int k0 = 0; k0 < K; k0 += 32) {
        const int nxt = k0 + 32;
        if (nxt < K) {
            load_stage(st ^ 1, nxt);
            CP_COMMIT();
        }

        const float* sA = sAb + st * SA_ST;
        const float* sB = sBb + st * SB_ST;
#pragma unroll
        for (int ks = 0; ks < 4; ks++) {
            const int kb = ks * 8;
            unsigned af[2][4];
#pragma unroll
            for (int mt = 0; mt < 2; mt++) {
                const int row = wm + mt * 16;
                af[mt][0] = tf32_bits(sA[(row + g    ) * 36 + kb + t    ]);
                af[mt][1] = tf32_bits(sA[(row + g + 8) * 36 + kb + t    ]);
                af[mt][2] = tf32_bits(sA[(row + g    ) * 36 + kb + t + 4]);
                af[mt][3] = tf32_bits(sA[(row + g + 8) * 36 + kb + t + 4]);
            }
            unsigned bf[8][2];
#pragma unroll
            for (int nt = 0; nt < 8; nt++) {
                const int col = wn + nt * 8 + g;
                bf[nt][0] = tf32_bits(sB[(kb + t    ) * 136 + col]);
                bf[nt][1] = tf32_bits(sB[(kb + t + 4) * 136 + col]);
            }
#pragma unroll
            for (int mt = 0; mt < 2; mt++)
#pragma unroll
                for (int nt = 0; nt < 8; nt++)
                    mma_tf32(acc[mt][nt], af[mt], bf[nt]);
        }

        if (nxt < K) CP_WAIT0();
        __syncthreads();
        st ^= 1;
    }

#pragma unroll
    for (int mt = 0; mt < 2; mt++) {
#pragma unroll
        for (int nt = 0; nt < 8; nt++) {
            const size_t row = (size_t)(m0 + wm + mt * 16 + g);
            const int    col = n0 + wn + nt * 8 + 2 * t;
            float2 lo = make_float2(acc[mt][nt][0], acc[mt][nt][1]);
            float2 hi = make_float2(acc[mt][nt][2], acc[mt][nt][3]);
            *reinterpret_cast<float2*>(&C[row * N + col])       = lo;
            *reinterpret_cast<float2*>(&C[(row + 8) * N + col]) = hi;
        }
    }
}

// ---------------------------------------------------------------------------
// Fused smolgen attention: one block per (b, q). 256 threads, 3 blocks/SM.
// a_q/a_k rows live in registers (invariant over the head loop).
// 4 barriers per head (K+V staged together).
// ---------------------------------------------------------------------------
__global__ __launch_bounds__(256, 3) void attn_kernel(
    const float* __restrict__ Q, const float* __restrict__ Kt,
    const float* __restrict__ V,
    const float* __restrict__ AQ, const float* __restrict__ AK,
    const float* __restrict__ AV, float* __restrict__ Out)
{
    extern __shared__ float smem[];
    float* sQ  = smem;                  // 1024
    float* sAv = sQ  + HH * HDD;        // 64*PAD
    float* sK  = sAv + TT * PAD;        // 64*PAD
    float* sV  = sK  + TT * PAD;        // 64*PAD
    float* sLog = sV + TT * PAD;        // 64
    float* sRed = sLog + TT;            // 256

    const int tid = threadIdx.x;
    const size_t row = (size_t)blockIdx.x;
    const int b = blockIdx.x >> 6;

    const int lk  = tid >> 2;           // 0..63
    const int lp  = tid & 3;            // 0..3
    const int od  = tid & 63;
    const int okp = tid >> 6;

    // Prologue: Q row + a_v tile to smem; a_q/a_k slices to registers.
    {
        const float4* src = reinterpret_cast<const float4*>(Q + row * DD);
        reinterpret_cast<float4*>(sQ)[tid] = src[tid];
    }
    {
        const float4* v4 = reinterpret_cast<const float4*>(AV + row * TT * HDD);
#pragma unroll
        for (int r = 0; r < 4; r++) {
            int f  = tid + r * 256;
            int kk = f >> 4;
            int c4 = (f & 15) * 4;
            *reinterpret_cast<float4*>(&sAv[kk * PAD + c4]) = v4[f];
        }
    }
    float aq_r[16], ak_r[16];
    {
        const float* aqp = AQ + row * TT * HDD + lk * HDD + lp;
        const float* akp = AK + row * TT * HDD + lk * HDD + lp;
#pragma unroll
        for (int i = 0; i < 16; i++) {
            aq_r[i] = aqp[4 * i];
            ak_r[i] = akp[4 * i];
        }
    }
    __syncthreads();

    for (int h = 0; h < HH; h++) {
        // stage K and V tiles for head h together
        {
            const float* kb = Kt + (size_t)b * TT * DD + h * HDD;
            const float* vb = V  + (size_t)b * TT * DD + h * HDD;
#pragma unroll
            for (int r = 0; r < 4; r++) {
                int f  = tid + r * 256;
                int kk = f >> 4;
                int c4 = (f & 15) * 4;
                float4 kv = *reinterpret_cast<const float4*>(kb + (size_t)kk * DD + c4);
                float4 vv = *reinterpret_cast<const float4*>(vb + (size_t)kk * DD + c4);
                *reinterpret_cast<float4*>(&sK[kk * PAD + c4]) = kv;
                *reinterpret_cast<float4*>(&sV[kk * PAD + c4]) = vv;
            }
        }
        __syncthreads();

        // logits: d = lp + 4*i (conflict-free)
        {
            const float* qh = sQ + h * HDD;
            float c = 0.f, bq = 0.f, bk = 0.f;
#pragma unroll
            for (int i = 0; i < 16; i++) {
                int d = lp + 4 * i;
                float kv = sK[lk * PAD + d];
                float qv = qh[d];
                c  += qv * kv;
                bq += aq_r[i] * kv;
                bk += qv * ak_r[i];
            }
            float l = c * 0.125f + bq + bk;
            l += __shfl_xor_sync(0xffffffffu, l, 1);
            l += __shfl_xor_sync(0xffffffffu, l, 2);
            if (lp == 0) sLog[lk] = l;
        }
        __syncthreads();

        // softmax over 64 logits (warp 0)
        if (tid < 32) {
            float a = sLog[tid], b2 = sLog[tid + 32];
            float m = fmaxf(a, b2);
#pragma unroll
            for (int o = 16; o; o >>= 1)
                m = fmaxf(m, __shfl_xor_sync(0xffffffffu, m, o));
            float ea = __expf(a - m), eb = __expf(b2 - m);
            float s = ea + eb;
#pragma unroll
            for (int o = 16; o; o >>= 1)
                s += __shfl_xor_sync(0xffffffffu, s, o);
            float inv = 1.0f / s;
            sLog[tid] = ea * inv;
            sLog[tid + 32] = eb * inv;
        }
        __syncthreads();

        // output: out[h][od] = sum_k p[k]*(V[k][od] + a_v[k][od])
        {
            float acc = 0.f;
#pragma unroll
            for (int i = 0; i < 16; i++) {
                int k = okp * 16 + i;
                float p = sLog[k];
                acc += p * (sV[k * PAD + od] + sAv[k * PAD + od]);
            }
            sRed[tid] = acc;
        }
        __syncthreads();
        if (tid < 64) {
            float o = sRed[tid] + sRed[tid + 64] + sRed[tid + 128] + sRed[tid + 192];
            Out[row * DD + h * HDD + tid] = o;
        }
        // next-iter sK/sV writes are ordered by the barrier after staging
    }
}

// ---------------------------------------------------------------------------
extern "C" void kernel_launch(void* const* d_in, const int* in_sizes, int n_in,
                              void* d_out, int out_size)
{
    const float* x  = (const float*)d_in[0];
    const float* aq = (const float*)d_in[1];
    const float* ak = (const float*)d_in[2];
    const float* av = (const float*)d_in[3];
    const float* Wq = (const float*)d_in[4];
    const float* Wk = (const float*)d_in[5];
    const float* Wv = (const float*)d_in[6];
    const float* Wo = (const float*)d_in[7];
    float* out = (float*)d_out;

    float *pq, *pk, *pv, *patt;
    cudaGetSymbolAddress((void**)&pq,   g_q);
    cudaGetSymbolAddress((void**)&pk,   g_k);
    cudaGetSymbolAddress((void**)&pv,   g_v);
    cudaGetSymbolAddress((void**)&patt, g_att);

    dim3 ggrid(DD / 128, BT / 128);   // (8, 64)

    cudaFuncSetAttribute((const void*)tf32_gemm_kernel,
                         cudaFuncAttributeMaxDynamicSharedMemorySize, GEMM_SMEM);

    tf32_gemm_kernel<<<ggrid, 256, GEMM_SMEM>>>(x, Wq, pq, BT, DD, DD);
    tf32_gemm_kernel<<<ggrid, 256, GEMM_SMEM>>>(x, Wk, pk, BT, DD, DD);
    tf32_gemm_kernel<<<ggrid, 256, GEMM_SMEM>>>(x, Wv, pv, BT, DD, DD);

    const int smem_bytes = (HH*HDD + 3 * TT * PAD + TT + 256) * (int)sizeof(float);
    cudaFuncSetAttribute((const void*)attn_kernel,
                         cudaFuncAttributeMaxDynamicSharedMemorySize, smem_bytes);
    attn_kernel<<<BT, 256, smem_bytes>>>(pq, pk, pv, aq, ak, av, patt);

    tf32_gemm_kernel<<<ggrid, 256, GEMM_SMEM>>>(patt, Wo, out, BT, DD, DD);
}